// round 16
// baseline (speedup 1.0000x reference)
#include <cuda_runtime.h>
#include <cstdint>

// SpatialPool fused: fm[16,512,38,38] f32 (NCHW) -> out[16,1444,9*512] f32
// out[b, h*38+w, (di*3+dj)*512 + c] = fm[b, c, clamp(h+di-1,0,37), clamp(w+dj-1,0,37)]
//
// TMA bulk-store variant: block owns TS=4 positions x 512 channels. Coalesced
// NCHW load -> PLAIN smem layout (each position's 2048B channel vector is
// contiguous). Scatter issues cp.async.bulk.global.shared::cta (async-proxy
// bulk store, 2048B per destination) from one lane per warp — bypasses the
// L1 store path and the per-lane STG stream entirely.
// Destination map is an exact partition of the output.

#define BB  16
#define CC  512
#define HH  38
#define WW  38
#define HWD 1444           // 38*38
#define OC4 1152           // 9*512/4 float4 per output row
#define CC4 128            // 512/4
#define ROW (WW * OC4)
#define TS  4
#define NT  361            // 1444 / 4 exact

__device__ __forceinline__ uint32_t smem_u32(const void* p) {
    uint32_t a;
    asm("{ .reg .u64 t; cvta.to.shared.u64 t, %1; cvt.u32.u64 %0, t; }"
        : "=r"(a) : "l"(p));
    return a;
}

__global__ __launch_bounds__(256)
void sp_fused_kernel(const float* __restrict__ fm, float4* __restrict__ out) {
    // plain layout: sm4[i*128 + j] -> position i's channels contiguous (2048B)
    __shared__ alignas(128) float4 sm4[TS * 128];   // 8 KB

    const int s0   = blockIdx.x * TS;
    const int b    = blockIdx.y;
    const int lane = threadIdx.x & 31;
    const int wrp  = threadIdx.x >> 5;

    // ---- load + transpose: li = lane>>3 (position), jsub = lane&7
    // STS: per 8-lane phase li fixed, j consecutive -> conflict-free STS.128
    {
        const int li   = lane >> 3;
        const int jsub = lane & 7;
        const float* src = fm + (size_t)b * CC * HWD + s0 + li;
        #pragma unroll
        for (int it = 0; it < 2; it++) {
            const int j = wrp * 16 + it * 8 + jsub;   // f4 channel group 0..127
            const float* p = src + (size_t)(4 * j) * HWD;
            float4 v;
            v.x = __ldcs(p);
            v.y = __ldcs(p + HWD);
            v.z = __ldcs(p + 2 * HWD);
            v.w = __ldcs(p + 3 * HWD);
            sm4[li * 128 + j] = v;
        }
    }
    __syncthreads();
    // make generic-proxy smem writes visible to the async (TMA) proxy
    asm volatile("fence.proxy.async.shared::cta;" ::: "memory");

    // ---- scatter: warp -> (position i, neighbor parity); lane 0 issues
    const int i    = wrp >> 1;          // 0..3
    const int wpar = wrp & 1;           // even/odd neighbors
    const int p    = s0 + i;
    const int hq   = p / WW;
    const int wq   = p - hq * WW;

    if (lane == 0) {
        const uint32_t ssrc = smem_u32(sm4) + i * 2048;

        // clamp-inverse destination classes: primary (hv) + duplicate (hd)
        // di=0 (d=-1): h=hq+1 if hq<37; dup h=0 if hq==0   (hq=37: none)
        // di=1 (d= 0): h=hq always
        // di=2 (d=+1): h=hq-1 if hq>0;  dup h=37 if hq==37 (hq=0: none)
        int  hoffP[3], hoffD[3];
        bool hv[3], hd[3];
        hv[0] = (hq < HH - 1);  hoffP[0] = (hq + 1) * ROW;
        hd[0] = (hq == 0);      hoffD[0] = 0;
        hv[1] = true;           hoffP[1] = hq * ROW;
        hd[1] = false;          hoffD[1] = 0;
        hv[2] = (hq > 0);       hoffP[2] = (hq - 1) * ROW;
        hd[2] = (hq == HH - 1); hoffD[2] = (HH - 1) * ROW;

        int  woffP[3], woffD[3];
        bool wv[3], wd[3];
        wv[0] = (wq < WW - 1);  woffP[0] = (wq + 1) * OC4;
        wd[0] = (wq == 0);      woffD[0] = 0;
        wv[1] = true;           woffP[1] = wq * OC4;
        wd[1] = false;          woffD[1] = 0;
        wv[2] = (wq > 0);       woffP[2] = (wq - 1) * OC4;
        wd[2] = (wq == WW - 1); woffD[2] = (WW - 1) * OC4;

        const int pbase0 = b * (HWD * OC4);   // f4 units, < 2^25

        #pragma unroll
        for (int n = 0; n < 9; n++) {
            if ((n & 1) != wpar) continue;    // parity split across 2 warps
            const int di = n / 3;
            const int dj = n - di * 3;
            const int base_n = pbase0 + n * CC4;

            if (hv[di] && wv[dj]) {
                const float4* g = out + (size_t)(base_n + hoffP[di] + woffP[dj]);
                asm volatile(
                    "cp.async.bulk.global.shared::cta.bulk_group [%0], [%1], 2048;"
                    :: "l"(g), "r"(ssrc) : "memory");
            }
            if (hd[di] && wv[dj]) {
                const float4* g = out + (size_t)(base_n + hoffD[di] + woffP[dj]);
                asm volatile(
                    "cp.async.bulk.global.shared::cta.bulk_group [%0], [%1], 2048;"
                    :: "l"(g), "r"(ssrc) : "memory");
            }
            if (hv[di] && wd[dj]) {
                const float4* g = out + (size_t)(base_n + hoffP[di] + woffD[dj]);
                asm volatile(
                    "cp.async.bulk.global.shared::cta.bulk_group [%0], [%1], 2048;"
                    :: "l"(g), "r"(ssrc) : "memory");
            }
            if (hd[di] && wd[dj]) {
                const float4* g = out + (size_t)(base_n + hoffD[di] + woffD[dj]);
                asm volatile(
                    "cp.async.bulk.global.shared::cta.bulk_group [%0], [%1], 2048;"
                    :: "l"(g), "r"(ssrc) : "memory");
            }
        }

        asm volatile("cp.async.bulk.commit_group;" ::: "memory");
        asm volatile("cp.async.bulk.wait_group 0;" ::: "memory");
    }
}

extern "C" void kernel_launch(void* const* d_in, const int* in_sizes, int n_in,
                              void* d_out, int out_size) {
    const float* fm = (const float*)d_in[0];
    float4* out = (float4*)d_out;

    dim3 grid(NT, BB);   // 361 x 16 = 5776 blocks
    sp_fused_kernel<<<grid, 256>>>(fm, out);
}